// round 12
// baseline (speedup 1.0000x reference)
#include <cuda_runtime.h>

// Problem constants
#define Bb   2
#define Cc   64
#define CIc  32
#define Tt   16
#define HWc  196
#define THWc 3136          // T*H*W
#define Nn   6272          // CI*H*W
#define NTc  100352        // CI*T*H*W == N*T (per-batch flat size)
#define BNT  200704        // B * NT
#define ZS   8             // spatial m-slices

// Scratch (device globals; no allocation allowed)
__device__ float g_F[6 * BNT];          // projections: [qs,ks,vs,qt,kt,vt]
__device__ float g_Y[BNT];              // ys + yt in (CI,T,H,W) flat layout per batch
__device__ float g_Sp[2 * 49 * 256];    // temporal score partials [b][chunk][t*16+s]
__device__ float g_A[512];              // temporal attention [b][t][s]
__device__ float g_Spart[ZS * 2 * 17 * Nn]; // spatial partials [z][b][t(0..15)+L(16)][n]

// ---------------------------------------------------------------------------
// Packed fp32x2 helpers (Blackwell FFMA2 — only reachable via PTX f32x2 ops)
// ---------------------------------------------------------------------------
typedef unsigned long long u64;

__device__ __forceinline__ u64 pk(float lo, float hi) {
    u64 r;
    asm("mov.b64 %0, {%1, %2};" : "=l"(r) : "f"(lo), "f"(hi));
    return r;
}
__device__ __forceinline__ float2 upk(u64 a) {
    float2 r;
    asm("mov.b64 {%0, %1}, %2;" : "=f"(r.x), "=f"(r.y) : "l"(a));
    return r;
}
__device__ __forceinline__ u64 fma2(u64 a, u64 b, u64 c) {
    u64 d;
    asm("fma.rn.f32x2 %0, %1, %2, %3;" : "=l"(d) : "l"(a), "l"(b), "l"(c));
    return d;
}
__device__ __forceinline__ u64 add2(u64 a, u64 b) {
    u64 d;
    asm("add.rn.f32x2 %0, %1, %2;" : "=l"(d) : "l"(a), "l"(b));
    return d;
}

// ---------------------------------------------------------------------------
// All six projections in ONE launch. grid.x = 784: [0,392) spatial qkv,
// [392,784) temporal qkv. 96 threads = 3 projs x 32 ci, 16 positions/block.
// ---------------------------------------------------------------------------
__global__ void k_proj6(const float* __restrict__ x,
                        const float* __restrict__ W0, const float* __restrict__ b0,
                        const float* __restrict__ W1, const float* __restrict__ b1,
                        const float* __restrict__ W2, const float* __restrict__ b2,
                        const float* __restrict__ W3, const float* __restrict__ b3,
                        const float* __restrict__ W4, const float* __restrict__ b4,
                        const float* __restrict__ W5, const float* __restrict__ b5) {
    __shared__ float Wt[64][97];                    // Wt[c][p3*32+ci] (pad 97)
    __shared__ __align__(16) float Xs[64][16];      // Xs[c][pos]
    __shared__ float bs[96];

    const int tid   = threadIdx.x;
    const int grp   = (blockIdx.x >= 392) ? 1 : 0;  // 0: spatial, 1: temporal
    const int pb    = blockIdx.x - grp * 392;
    const int b     = pb / 196;
    const int thw0  = (pb % 196) * 16;
    const int p3    = tid >> 5;
    const int ci    = tid & 31;
    const int P     = grp * 3 + p3;

    const float* W;
    const float* bias;
    switch (P) {
        case 0:  W = W0; bias = b0; break;
        case 1:  W = W1; bias = b1; break;
        case 2:  W = W2; bias = b2; break;
        case 3:  W = W3; bias = b3; break;
        case 4:  W = W4; bias = b4; break;
        default: W = W5; bias = b5; break;
    }

    // Coalesced weight load: 512 float4 per W, each 32-thread group loads its own.
    {
        const float4* Wg = reinterpret_cast<const float4*>(W);
        #pragma unroll
        for (int it = 0; it < 16; ++it) {
            const int i = ci + it * 32;           // float4 index 0..511
            float4 w = Wg[i];
            const int r  = i >> 4;                // ci' row (16 float4 per row)
            const int c0 = (i & 15) * 4;          // channel base
            Wt[c0 + 0][p3 * 32 + r] = w.x;
            Wt[c0 + 1][p3 * 32 + r] = w.y;
            Wt[c0 + 2][p3 * 32 + r] = w.z;
            Wt[c0 + 3][p3 * 32 + r] = w.w;
        }
    }
    bs[tid] = __ldg(&bias[ci]);

    // x tile: 64 channels x 16 positions = 256 float4
    const float4* xg = reinterpret_cast<const float4*>(x + (size_t)b * (Cc * THWc) + thw0);
    for (int i = tid; i < 256; i += 96) {
        int c = i >> 2, j = i & 3;
        reinterpret_cast<float4*>(&Xs[c][0])[j] = xg[c * (THWc / 4) + j];
    }
    __syncthreads();

    float acc[16];
    const float bv = bs[tid];
    #pragma unroll
    for (int p = 0; p < 16; ++p) acc[p] = bv;

    for (int c = 0; c < 64; ++c) {
        const float w = Wt[c][tid];
        #pragma unroll
        for (int j = 0; j < 4; ++j) {
            float4 xv = reinterpret_cast<const float4*>(&Xs[c][0])[j];
            acc[4 * j + 0] = fmaf(w, xv.x, acc[4 * j + 0]);
            acc[4 * j + 1] = fmaf(w, xv.y, acc[4 * j + 1]);
            acc[4 * j + 2] = fmaf(w, xv.z, acc[4 * j + 2]);
            acc[4 * j + 3] = fmaf(w, xv.w, acc[4 * j + 3]);
        }
    }

    float* dst = g_F + (size_t)P * BNT + (size_t)b * NTc + ci * THWc + thw0;
    #pragma unroll
    for (int j = 0; j < 4; ++j) {
        reinterpret_cast<float4*>(dst)[j] =
            make_float4(acc[4 * j], acc[4 * j + 1], acc[4 * j + 2], acc[4 * j + 3]);
    }
}

// ---------------------------------------------------------------------------
// Spatial attention: 2 queries/thread (64 threads, 128 queries/block), one
// double-buffered K/V tile. q pre-scaled by 0.25*log2(e) so exp is a single
// EX2 (exp2f). grid (49, 2, ZS). Partial exp-sums (no max-subtraction;
// validated R1) -> g_Spart.
// ---------------------------------------------------------------------------
__global__ void __launch_bounds__(64) k_spatial() {
    __shared__ __align__(16) float Ks[2][16][64];
    __shared__ __align__(16) float Vs[2][16][64];

    const int tid = threadIdx.x;          // 0..63
    const int b   = blockIdx.y;
    const int z   = blockIdx.z;
    const int n0  = blockIdx.x * 128 + tid;   // query 0
    const int n1  = n0 + 64;                   // query 1

    const float* Fq = g_F + 0 * BNT + (size_t)b * NTc;
    const float* Fk = g_F + 1 * BNT + (size_t)b * NTc;
    const float* Fv = g_F + 2 * BNT + (size_t)b * NTc;

    const float QSCALE = 0.25f * 1.4426950408889634f;   // fold scale & log2e
    u64 qq0[16], qq1[16];
    #pragma unroll
    for (int t = 0; t < 16; ++t) {
        float v0 = QSCALE * Fq[t * Nn + n0];
        float v1 = QSCALE * Fq[t * Nn + n1];
        qq0[t] = pk(v0, v0);
        qq1[t] = pk(v1, v1);
    }

    u64 acc0[16], acc1[16];           // {even-m partial, odd-m partial}
    #pragma unroll
    for (int t = 0; t < 16; ++t) { acc0[t] = 0ULL; acc1[t] = 0ULL; }
    u64 L0 = 0ULL, L1 = 0ULL;

    // preload first tile into buf 0 (256 float4 per tensor, 64 threads)
    {
        const int m0 = z * 64;
        #pragma unroll
        for (int r = 0; r < 4; ++r) {
            const int i = tid + r * 64;           // 0..255
            const int t = i >> 4, c4 = i & 15;
            reinterpret_cast<float4*>(&Ks[0][t][0])[c4] =
                reinterpret_cast<const float4*>(Fk + t * Nn + m0)[c4];
            reinterpret_cast<float4*>(&Vs[0][t][0])[c4] =
                reinterpret_cast<const float4*>(Fv + t * Nn + m0)[c4];
        }
    }
    __syncthreads();

    int buf = 0;
    for (int tile = z; tile < 98; tile += ZS, buf ^= 1) {
        const int nxt = tile + ZS;
        if (nxt < 98) {                            // prefetch next tile
            const int m0 = nxt * 64;
            #pragma unroll
            for (int r = 0; r < 4; ++r) {
                const int i = tid + r * 64;
                const int t = i >> 4, c4 = i & 15;
                reinterpret_cast<float4*>(&Ks[buf ^ 1][t][0])[c4] =
                    reinterpret_cast<const float4*>(Fk + t * Nn + m0)[c4];
                reinterpret_cast<float4*>(&Vs[buf ^ 1][t][0])[c4] =
                    reinterpret_cast<const float4*>(Fv + t * Nn + m0)[c4];
            }
        }

        const float (*Kb)[64] = Ks[buf];
        const float (*Vb)[64] = Vs[buf];

        #pragma unroll 2
        for (int mm = 0; mm < 64; mm += 4) {
            // 4 independent chains: (query0, query1) x (m-pair01, m-pair23)
            u64 s0A = 0ULL, s0B = 0ULL, s1A = 0ULL, s1B = 0ULL;
            #pragma unroll
            for (int t = 0; t < 16; ++t) {
                ulonglong2 kv = *reinterpret_cast<const ulonglong2*>(&Kb[t][mm]);
                s0A = fma2(qq0[t], kv.x, s0A);
                s0B = fma2(qq0[t], kv.y, s0B);
                s1A = fma2(qq1[t], kv.x, s1A);
                s1B = fma2(qq1[t], kv.y, s1B);
            }
            float2 q0s01 = upk(s0A), q0s23 = upk(s0B);
            float2 q1s01 = upk(s1A), q1s23 = upk(s1B);

            u64 p0a = pk(exp2f(q0s01.x), exp2f(q0s01.y));
            u64 p0b = pk(exp2f(q0s23.x), exp2f(q0s23.y));
            u64 p1a = pk(exp2f(q1s01.x), exp2f(q1s01.y));
            u64 p1b = pk(exp2f(q1s23.x), exp2f(q1s23.y));
            L0 = add2(L0, add2(p0a, p0b));
            L1 = add2(L1, add2(p1a, p1b));

            #pragma unroll
            for (int t = 0; t < 16; ++t) {
                ulonglong2 vv = *reinterpret_cast<const ulonglong2*>(&Vb[t][mm]);
                u64 a0 = acc0[t];
                a0 = fma2(p0a, vv.x, a0);
                a0 = fma2(p0b, vv.y, a0);
                acc0[t] = a0;
                u64 a1 = acc1[t];
                a1 = fma2(p1a, vv.x, a1);
                a1 = fma2(p1b, vv.y, a1);
                acc1[t] = a1;
            }
        }
        __syncthreads();
    }

    float* Pp = g_Spart + ((size_t)(z * 2 + b) * 17) * Nn;
    float2 Lp0 = upk(L0), Lp1 = upk(L1);
    Pp[16 * Nn + n0] = Lp0.x + Lp0.y;
    Pp[16 * Nn + n1] = Lp1.x + Lp1.y;
    #pragma unroll
    for (int t = 0; t < 16; ++t) {
        float2 a0 = upk(acc0[t]);
        float2 a1 = upk(acc1[t]);
        Pp[t * Nn + n0] = a0.x + a0.y;
        Pp[t * Nn + n1] = a1.x + a1.y;
    }
}

// ---------------------------------------------------------------------------
// Spatial combine: one thread per (b, n); computes L once, writes all 16
// spatial values (=) at flat [t*Nn + n] (the (B,T,N)-view placement).
// grid (49, 2) x 128.
// ---------------------------------------------------------------------------
__global__ void __launch_bounds__(128) k_scomb() {
    const int tid = threadIdx.x;
    const int b   = blockIdx.y;
    const int n   = blockIdx.x * 128 + tid;       // n in [0, Nn)

    float L = 0.f;
    #pragma unroll
    for (int z = 0; z < ZS; ++z)
        L += g_Spart[((size_t)(z * 2 + b) * 17 + 16) * Nn + n];
    const float inv = 1.f / L;

    float* Yb = g_Y + (size_t)b * NTc;
    #pragma unroll
    for (int t = 0; t < 16; ++t) {
        float a = 0.f;
        #pragma unroll
        for (int z = 0; z < ZS; ++z)
            a += g_Spart[((size_t)(z * 2 + b) * 17 + t) * Nn + n];
        Yb[t * Nn + n] = a * inv;
    }
}

// ---------------------------------------------------------------------------
// Temporal score partials: grid (49, 2), 256 threads = (t,s) pairs.
// Coalesced float4 loads -> smem transpose (pad 132) -> vectorized dots.
// ---------------------------------------------------------------------------
__global__ void __launch_bounds__(256) k_tempS() {
    __shared__ __align__(16) float Qs[16][132];
    __shared__ __align__(16) float Ks2[16][132];

    const int tid = threadIdx.x;
    const int b   = blockIdx.y;
    const int n0  = blockIdx.x * 128;

    const float* Q = g_F + 3 * BNT + (size_t)b * NTc + (size_t)n0 * 16;
    const float* K = g_F + 4 * BNT + (size_t)b * NTc + (size_t)n0 * 16;

    #pragma unroll
    for (int r = 0; r < 2; ++r) {
        const int j  = tid + r * 256;        // float4 index
        const int n  = j >> 2;
        const int t0 = (j & 3) * 4;
        float4 qv = reinterpret_cast<const float4*>(Q)[j];
        Qs[t0 + 0][n] = qv.x; Qs[t0 + 1][n] = qv.y;
        Qs[t0 + 2][n] = qv.z; Qs[t0 + 3][n] = qv.w;
        float4 kv = reinterpret_cast<const float4*>(K)[j];
        Ks2[t0 + 0][n] = kv.x; Ks2[t0 + 1][n] = kv.y;
        Ks2[t0 + 2][n] = kv.z; Ks2[t0 + 3][n] = kv.w;
    }
    __syncthreads();

    const int t = tid >> 4, s = tid & 15;
    u64 sa = 0ULL, sb = 0ULL, sc = 0ULL, sd = 0ULL;
    #pragma unroll 8
    for (int j = 0; j < 32; j += 2) {
        ulonglong2 q4 = *reinterpret_cast<const ulonglong2*>(&Qs[t][4 * j]);
        ulonglong2 k4 = *reinterpret_cast<const ulonglong2*>(&Ks2[s][4 * j]);
        sa = fma2(q4.x, k4.x, sa);
        sb = fma2(q4.y, k4.y, sb);
        ulonglong2 q5 = *reinterpret_cast<const ulonglong2*>(&Qs[t][4 * j + 4]);
        ulonglong2 k5 = *reinterpret_cast<const ulonglong2*>(&Ks2[s][4 * j + 4]);
        sc = fma2(q5.x, k5.x, sc);
        sd = fma2(q5.y, k5.y, sd);
    }
    float2 r = upk(add2(add2(sa, sb), add2(sc, sd)));
    g_Sp[((size_t)b * 49 + blockIdx.x) * 256 + tid] = r.x + r.y;
}

// Reduce partials + softmax: 512 threads, one per (b,t,s). Coalesced sweeps
// over the 49 chunks; softmax over s via shfl within 16-thread groups.
__global__ void __launch_bounds__(512) k_tsoft() {
    const int tid = threadIdx.x;         // b = tid>>8, ts = tid&255
    const int b   = tid >> 8;
    const int ts  = tid & 255;
    float a = 0.f;
    #pragma unroll
    for (int c = 0; c < 49; ++c) a += g_Sp[((size_t)b * 49 + c) * 256 + ts];

    float m = a;
    #pragma unroll
    for (int off = 1; off < 16; off <<= 1)
        m = fmaxf(m, __shfl_xor_sync(0xffffffffu, m, off));
    float e = __expf(0.25f * (a - m));
    float sum = e;
    #pragma unroll
    for (int off = 1; off < 16; off <<= 1)
        sum += __shfl_xor_sync(0xffffffffu, sum, off);
    g_A[tid] = e / sum;
}

// Apply temporal attention: 2 threads per n (8 t's each, disjoint float4
// writes); ADDS (+=) into g_Y at flat [n*16 + t] (the (B,N,T)-view
// placement) — must run AFTER k_scomb. grid 98 x 256.
__global__ void k_tapply() {
    __shared__ float sA[512];
    const int tid = threadIdx.x;
    sA[tid]       = g_A[tid];
    sA[tid + 256] = g_A[tid + 256];
    __syncthreads();

    const int idx2 = blockIdx.x * 256 + tid;     // 0 .. 25087
    const int ng   = idx2 >> 1;                  // global n index (0..12543)
    const int half = idx2 & 1;
    const int b    = ng / Nn;
    const int n    = ng - b * Nn;

    const float4* vp = reinterpret_cast<const float4*>(g_F + 5 * BNT + (size_t)b * NTc + n * 16);
    float v[16];
    #pragma unroll
    for (int j = 0; j < 4; ++j) {
        float4 v4 = vp[j];
        v[4 * j] = v4.x; v[4 * j + 1] = v4.y; v[4 * j + 2] = v4.z; v[4 * j + 3] = v4.w;
    }
    const float* A = &sA[b * 256];
    float4* yp = reinterpret_cast<float4*>(g_Y + (size_t)b * NTc + n * 16);
    #pragma unroll
    for (int jj = 0; jj < 2; ++jj) {
        const int j = half * 2 + jj;
        float4 y4 = yp[j];
        float o[4];
        #pragma unroll
        for (int k = 0; k < 4; ++k) {
            const int t = 4 * j + k;
            float a = 0.f;
            #pragma unroll
            for (int s = 0; s < 16; ++s) a = fmaf(A[t * 16 + s], v[s], a);
            o[k] = a;
        }
        y4.x += o[0]; y4.y += o[1]; y4.z += o[2]; y4.w += o[3];
        yp[j] = y4;
    }
}

// ---------------------------------------------------------------------------
// Output projection + residual: grid 784 (8 positions each), 64 threads = o.
// ---------------------------------------------------------------------------
__global__ void __launch_bounds__(64) k_out(const float* __restrict__ x,
                                            const float* __restrict__ Ww,
                                            const float* __restrict__ bw,
                                            float* __restrict__ out) {
    __shared__ float Wt[32][65];
    __shared__ __align__(16) float Ys[32][8];

    const int tid  = threadIdx.x;                 // output channel o
    const int pb   = blockIdx.x;
    const int b    = pb / 392;
    const int thw0 = (pb % 392) * 8;

    // Coalesced weight load: 512 float4, 8 per thread. Ww is [64][32].
    {
        const float4* Wg = reinterpret_cast<const float4*>(Ww);
        #pragma unroll
        for (int k = 0; k < 8; ++k) {
            const int i = tid + k * 64;           // float4 index 0..511
            float4 w = Wg[i];
            const int o  = i >> 3;                // 8 float4 per o-row
            const int c0 = (i & 7) * 4;
            Wt[c0 + 0][o] = w.x;
            Wt[c0 + 1][o] = w.y;
            Wt[c0 + 2][o] = w.z;
            Wt[c0 + 3][o] = w.w;
        }
    }

    const float* Yb = g_Y + (size_t)b * NTc + thw0;
    {   // 32 ci x 8 pos = 64 float4, 1 per thread
        const int ci = tid >> 1, j = tid & 1;
        reinterpret_cast<float4*>(&Ys[ci][0])[j] =
            reinterpret_cast<const float4*>(Yb + ci * THWc)[j];
    }
    __syncthreads();

    float acc[8];
    const float bv = __ldg(&bw[tid]);
    #pragma unroll
    for (int p = 0; p < 8; ++p) acc[p] = bv;

    #pragma unroll 8
    for (int ci = 0; ci < 32; ++ci) {
        const float w = Wt[ci][tid];
        #pragma unroll
        for (int j = 0; j < 2; ++j) {
            float4 yv = reinterpret_cast<const float4*>(&Ys[ci][0])[j];
            acc[4 * j + 0] = fmaf(w, yv.x, acc[4 * j + 0]);
            acc[4 * j + 1] = fmaf(w, yv.y, acc[4 * j + 1]);
            acc[4 * j + 2] = fmaf(w, yv.z, acc[4 * j + 2]);
            acc[4 * j + 3] = fmaf(w, yv.w, acc[4 * j + 3]);
        }
    }

    const size_t off = (size_t)b * (Cc * THWc) + (size_t)tid * THWc + thw0;
    const float4* xg = reinterpret_cast<const float4*>(x + off);
    float4* og = reinterpret_cast<float4*>(out + off);
    #pragma unroll
    for (int j = 0; j < 2; ++j) {
        float4 xv = xg[j];
        og[j] = make_float4(acc[4 * j + 0] + xv.x, acc[4 * j + 1] + xv.y,
                            acc[4 * j + 2] + xv.z, acc[4 * j + 3] + xv.w);
    }
}

// ---------------------------------------------------------------------------
extern "C" void kernel_launch(void* const* d_in, const int* in_sizes, int n_in,
                              void* d_out, int out_size) {
    (void)in_sizes; (void)n_in; (void)out_size;
    const float* x   = (const float*)d_in[0];
    const float* Wqs = (const float*)d_in[1];  const float* bqs = (const float*)d_in[2];
    const float* Wks = (const float*)d_in[3];  const float* bks = (const float*)d_in[4];
    const float* Wvs = (const float*)d_in[5];  const float* bvs = (const float*)d_in[6];
    const float* Wqt = (const float*)d_in[7];  const float* bqt = (const float*)d_in[8];
    const float* Wkt = (const float*)d_in[9];  const float* bkt = (const float*)d_in[10];
    const float* Wvt = (const float*)d_in[11]; const float* bvt = (const float*)d_in[12];
    const float* Ww  = (const float*)d_in[13]; const float* bw  = (const float*)d_in[14];
    float* out = (float*)d_out;

    k_proj6<<<784, 96>>>(x, Wqs, bqs, Wks, bks, Wvs, bvs,
                            Wqt, bqt, Wkt, bkt, Wvt, bvt);
    k_spatial<<<dim3(49, 2, ZS), 64>>>();
    k_tempS<<<dim3(49, 2), 256>>>();
    k_tsoft<<<1, 512>>>();
    k_scomb<<<dim3(49, 2), 128>>>();      // spatial (=) at t*Nn+n
    k_tapply<<<98, 256>>>();              // temporal (+=) at n*16+t, AFTER scomb
    k_out<<<784, 64>>>(x, Ww, bw, out);
}

// round 14
// speedup vs baseline: 2.5656x; 2.5656x over previous
#include <cuda_runtime.h>
#include <cuda_bf16.h>
#include <cstdint>

#define Cc   64
#define THWc 3136
#define Nn   6272
#define NTc  100352
#define BNT  200704
#define ZS   8

__device__ float g_F[6 * BNT];            // [qs,ks,vs,qt,kt,vt]
__device__ float g_Y[BNT];
__device__ float g_Sp[2 * 49 * 256];
__device__ float g_A[512];
__device__ float g_Spart[ZS * 2 * 17 * Nn];   // [z][b][t(0..15)+L(16)][n]
__device__ uint32_t g_Qbf[2 * Nn * 8];    // [b][n][j]: bf16x2 {q'(t=2j), q'(2j+1)}, q'=0.25*log2e*q
__device__ uint32_t g_Kbf[2 * Nn * 8];    // [b][m][j]: bf16x2 {k(2j), k(2j+1)}
__device__ uint32_t g_Vbf[2 * 16 * (Nn / 2)]; // [b][t][mp]: bf16x2 {v(m=2mp), v(2mp+1)}

typedef unsigned long long u64;

// ---- f32x2 helpers (k_tempS) ----
__device__ __forceinline__ float2 upk(u64 a) {
    float2 r; asm("mov.b64 {%0, %1}, %2;" : "=f"(r.x), "=f"(r.y) : "l"(a)); return r;
}
__device__ __forceinline__ u64 fma2(u64 a, u64 b, u64 c) {
    u64 d; asm("fma.rn.f32x2 %0, %1, %2, %3;" : "=l"(d) : "l"(a), "l"(b), "l"(c)); return d;
}
__device__ __forceinline__ u64 add2(u64 a, u64 b) {
    u64 d; asm("add.rn.f32x2 %0, %1, %2;" : "=l"(d) : "l"(a), "l"(b)); return d;
}

__device__ __forceinline__ float ex2f(float x) {
    float r; asm("ex2.approx.f32 %0, %1;" : "=f"(r) : "f"(x)); return r;
}
__device__ __forceinline__ uint32_t pkbf2(float lo, float hi) {
    uint32_t r;  // lower 16 bits = lo
    asm("cvt.rn.bf16x2.f32 %0, %1, %2;" : "=r"(r) : "f"(hi), "f"(lo));
    return r;
}
// mma.sync m16n8k16 bf16 (row.col), D += A*B
__device__ __forceinline__ void hmma(float4& d, const uint32_t* a, const uint32_t* bfr) {
    asm volatile(
        "mma.sync.aligned.m16n8k16.row.col.f32.bf16.bf16.f32 "
        "{%0,%1,%2,%3}, {%4,%5,%6,%7}, {%8,%9}, {%0,%1,%2,%3};"
        : "+f"(d.x), "+f"(d.y), "+f"(d.z), "+f"(d.w)
        : "r"(a[0]), "r"(a[1]), "r"(a[2]), "r"(a[3]), "r"(bfr[0]), "r"(bfr[1]));
}

// ---------------------------------------------------------------------------
// Six projections (R11-proven). grid 784 x 96.
// ---------------------------------------------------------------------------
__global__ void k_proj6(const float* __restrict__ x,
                        const float* __restrict__ W0, const float* __restrict__ b0,
                        const float* __restrict__ W1, const float* __restrict__ b1,
                        const float* __restrict__ W2, const float* __restrict__ b2,
                        const float* __restrict__ W3, const float* __restrict__ b3,
                        const float* __restrict__ W4, const float* __restrict__ b4,
                        const float* __restrict__ W5, const float* __restrict__ b5) {
    __shared__ float Wt[64][97];
    __shared__ __align__(16) float Xs[64][16];
    __shared__ float bs[96];

    const int tid  = threadIdx.x;
    const int grp  = (blockIdx.x >= 392) ? 1 : 0;
    const int pb   = blockIdx.x - grp * 392;
    const int b    = pb / 196;
    const int thw0 = (pb % 196) * 16;
    const int p3   = tid >> 5;
    const int ci   = tid & 31;
    const int P    = grp * 3 + p3;

    const float* W; const float* bias;
    switch (P) {
        case 0:  W = W0; bias = b0; break;
        case 1:  W = W1; bias = b1; break;
        case 2:  W = W2; bias = b2; break;
        case 3:  W = W3; bias = b3; break;
        case 4:  W = W4; bias = b4; break;
        default: W = W5; bias = b5; break;
    }
    {
        const float4* Wg = reinterpret_cast<const float4*>(W);
        #pragma unroll
        for (int it = 0; it < 16; ++it) {
            const int i = ci + it * 32;
            float4 w = Wg[i];
            const int r = i >> 4, c0 = (i & 15) * 4;
            Wt[c0 + 0][p3 * 32 + r] = w.x;
            Wt[c0 + 1][p3 * 32 + r] = w.y;
            Wt[c0 + 2][p3 * 32 + r] = w.z;
            Wt[c0 + 3][p3 * 32 + r] = w.w;
        }
    }
    bs[tid] = __ldg(&bias[ci]);

    const float4* xg = reinterpret_cast<const float4*>(x + (size_t)b * (Cc * THWc) + thw0);
    for (int i = tid; i < 256; i += 96) {
        int c = i >> 2, j = i & 3;
        reinterpret_cast<float4*>(&Xs[c][0])[j] = xg[c * (THWc / 4) + j];
    }
    __syncthreads();

    float acc[16];
    const float bv = bs[tid];
    #pragma unroll
    for (int p = 0; p < 16; ++p) acc[p] = bv;

    for (int c = 0; c < 64; ++c) {
        const float w = Wt[c][tid];
        #pragma unroll
        for (int j = 0; j < 4; ++j) {
            float4 xv = reinterpret_cast<const float4*>(&Xs[c][0])[j];
            acc[4 * j + 0] = fmaf(w, xv.x, acc[4 * j + 0]);
            acc[4 * j + 1] = fmaf(w, xv.y, acc[4 * j + 1]);
            acc[4 * j + 2] = fmaf(w, xv.z, acc[4 * j + 2]);
            acc[4 * j + 3] = fmaf(w, xv.w, acc[4 * j + 3]);
        }
    }
    float* dst = g_F + (size_t)P * BNT + (size_t)b * NTc + ci * THWc + thw0;
    #pragma unroll
    for (int j = 0; j < 4; ++j)
        reinterpret_cast<float4*>(dst)[j] =
            make_float4(acc[4 * j], acc[4 * j + 1], acc[4 * j + 2], acc[4 * j + 3]);
}

// ---------------------------------------------------------------------------
// bf16 staging. grid (49, 2) x 256. Q pre-scaled by 0.25*log2e.
// ---------------------------------------------------------------------------
__global__ void __launch_bounds__(256) k_prep() {
    const int tid = threadIdx.x, b = blockIdx.y, c0 = blockIdx.x * 128;
    const float QS = 0.25f * 1.4426950408889634f;

    if (tid < 128) {                       // Q transpose-gather
        const int n = c0 + tid;
        const float* Fq = g_F + 0 * BNT + (size_t)b * NTc;
        uint32_t r[8];
        #pragma unroll
        for (int j = 0; j < 8; ++j)
            r[j] = pkbf2(QS * Fq[(2 * j) * Nn + n], QS * Fq[(2 * j + 1) * Nn + n]);
        uint4* dst = reinterpret_cast<uint4*>(&g_Qbf[((size_t)b * Nn + n) * 8]);
        dst[0] = make_uint4(r[0], r[1], r[2], r[3]);
        dst[1] = make_uint4(r[4], r[5], r[6], r[7]);
    } else {                               // K transpose-gather
        const int m = c0 + tid - 128;
        const float* Fk = g_F + 1 * BNT + (size_t)b * NTc;
        uint32_t r[8];
        #pragma unroll
        for (int j = 0; j < 8; ++j)
            r[j] = pkbf2(Fk[(2 * j) * Nn + m], Fk[(2 * j + 1) * Nn + m]);
        uint4* dst = reinterpret_cast<uint4*>(&g_Kbf[((size_t)b * Nn + m) * 8]);
        dst[0] = make_uint4(r[0], r[1], r[2], r[3]);
        dst[1] = make_uint4(r[4], r[5], r[6], r[7]);
    }
    // V copy: 16 t x 128 m per block (all 256 threads)
    const int t = tid >> 4, seg = tid & 15;
    const float* Fv = g_F + 2 * BNT + (size_t)b * NTc + t * Nn + c0 + seg * 8;
    float4 a = reinterpret_cast<const float4*>(Fv)[0];
    float4 c = reinterpret_cast<const float4*>(Fv)[1];
    uint4 o;
    o.x = pkbf2(a.x, a.y); o.y = pkbf2(a.z, a.w);
    o.z = pkbf2(c.x, c.y); o.w = pkbf2(c.z, c.w);
    *reinterpret_cast<uint4*>(&g_Vbf[((size_t)(b * 16 + t)) * (Nn / 2) + ((c0 + seg * 8) >> 1)]) = o;
}

// ---------------------------------------------------------------------------
// Spatial flash attention on mma.sync (HMMA bf16). grid (49, 2, ZS) x 128.
// Warp = 32 queries (two 16-row A tiles). Per 16-m chunk: 2x2 MMA1 scores,
// exp2+pack in regs (D1 fragment layout == A fragment layout), 2x2 MMA2
// into persistent f32 accumulators. m-sliced across z; partial exp-sums ->
// g_Spart (no max-subtraction; validated R1). k_scomb normalizes.
// ---------------------------------------------------------------------------
__global__ void __launch_bounds__(128) k_sfmma() {
    const int tid  = threadIdx.x;
    const int w    = tid >> 5;
    const int lane = tid & 31;
    const int g    = lane >> 2;        // group (row)
    const int tig  = lane & 3;         // thread-in-group
    const int b    = blockIdx.y;
    const int z    = blockIdx.z;
    const int n0w  = blockIdx.x * 128 + w * 32;

    // Q fragments: 2 q-tiles (rows n0w.. / n0w+16..)
    uint32_t A[2][4];
    #pragma unroll
    for (int qt = 0; qt < 2; ++qt) {
        const uint32_t* Qp = &g_Qbf[((size_t)b * Nn + n0w + 16 * qt) * 8];
        A[qt][0] = Qp[(size_t)g * 8 + tig];
        A[qt][1] = Qp[(size_t)(g + 8) * 8 + tig];
        A[qt][2] = Qp[(size_t)g * 8 + tig + 4];
        A[qt][3] = Qp[(size_t)(g + 8) * 8 + tig + 4];
    }

    float4 acc[2][2];                  // [qt][t-tile], persistent f32 accum
    #pragma unroll
    for (int i = 0; i < 2; ++i)
        #pragma unroll
        for (int j = 0; j < 2; ++j) acc[i][j] = make_float4(0.f, 0.f, 0.f, 0.f);
    float Llo[2] = {0.f, 0.f}, Lhi[2] = {0.f, 0.f};

    const uint32_t* Kb = &g_Kbf[(size_t)b * Nn * 8];
    const uint32_t* Vb = &g_Vbf[(size_t)b * 16 * (Nn / 2)];

    for (int i = 0; i < 49; ++i) {
        const int m0 = (z * 49 + i) * 16;

        // K fragments (B of MMA1): tile mt covers m0+8*mt.. ; col n = m
        uint32_t Kf[2][2], Vf[2][2];
        Kf[0][0] = Kb[(size_t)(m0 + g) * 8 + tig];
        Kf[0][1] = Kb[(size_t)(m0 + g) * 8 + tig + 4];
        Kf[1][0] = Kb[(size_t)(m0 + 8 + g) * 8 + tig];
        Kf[1][1] = Kb[(size_t)(m0 + 8 + g) * 8 + tig + 4];
        // V fragments (B of MMA2): tile tt covers t = 8*tt + g; k rows = m
        Vf[0][0] = Vb[(size_t)g * (Nn / 2) + (m0 >> 1) + tig];
        Vf[0][1] = Vb[(size_t)g * (Nn / 2) + (m0 >> 1) + tig + 4];
        Vf[1][0] = Vb[(size_t)(8 + g) * (Nn / 2) + (m0 >> 1) + tig];
        Vf[1][1] = Vb[(size_t)(8 + g) * (Nn / 2) + (m0 >> 1) + tig + 4];

        #pragma unroll
        for (int qt = 0; qt < 2; ++qt) {
            float4 D0 = make_float4(0.f, 0.f, 0.f, 0.f);
            float4 D1 = make_float4(0.f, 0.f, 0.f, 0.f);
            hmma(D0, A[qt], Kf[0]);
            hmma(D1, A[qt], Kf[1]);

            float e00 = ex2f(D0.x), e01 = ex2f(D0.y);
            float e02 = ex2f(D0.z), e03 = ex2f(D0.w);
            float e10 = ex2f(D1.x), e11 = ex2f(D1.y);
            float e12 = ex2f(D1.z), e13 = ex2f(D1.w);
            Llo[qt] += (e00 + e01) + (e10 + e11);
            Lhi[qt] += (e02 + e03) + (e12 + e13);

            // P fragment: D layout maps directly to A layout
            uint32_t Pf[4];
            Pf[0] = pkbf2(e00, e01);   // rows g,   m cols 2tig..  (tile0)
            Pf[1] = pkbf2(e02, e03);   // rows g+8
            Pf[2] = pkbf2(e10, e11);   // m cols +8 (tile1)
            Pf[3] = pkbf2(e12, e13);

            hmma(acc[qt][0], Pf, Vf[0]);
            hmma(acc[qt][1], Pf, Vf[1]);
        }
    }

    // reduce L over the 4 lanes of each group (they cover disjoint m)
    #pragma unroll
    for (int qt = 0; qt < 2; ++qt) {
        #pragma unroll
        for (int off = 1; off < 4; off <<= 1) {
            Llo[qt] += __shfl_xor_sync(0xffffffffu, Llo[qt], off);
            Lhi[qt] += __shfl_xor_sync(0xffffffffu, Lhi[qt], off);
        }
    }

    float* Pp = g_Spart + ((size_t)(z * 2 + b) * 17) * Nn;
    if (tig == 0) {
        #pragma unroll
        for (int qt = 0; qt < 2; ++qt) {
            Pp[16 * Nn + n0w + 16 * qt + g]     = Llo[qt];
            Pp[16 * Nn + n0w + 16 * qt + g + 8] = Lhi[qt];
        }
    }
    #pragma unroll
    for (int qt = 0; qt < 2; ++qt) {
        const int n = n0w + 16 * qt + g;
        #pragma unroll
        for (int tt = 0; tt < 2; ++tt) {
            const int t0 = 8 * tt + 2 * tig;
            Pp[(size_t)t0 * Nn + n]           = acc[qt][tt].x;
            Pp[(size_t)(t0 + 1) * Nn + n]     = acc[qt][tt].y;
            Pp[(size_t)t0 * Nn + n + 8]       = acc[qt][tt].z;
            Pp[(size_t)(t0 + 1) * Nn + n + 8] = acc[qt][tt].w;
        }
    }
}

// ---------------------------------------------------------------------------
// Spatial combine (R11-proven): one thread per (b, n), ZS partials,
// writes (=) at flat [t*Nn + n]. grid (49, 2) x 128.
// ---------------------------------------------------------------------------
__global__ void __launch_bounds__(128) k_scomb() {
    const int tid = threadIdx.x;
    const int b   = blockIdx.y;
    const int n   = blockIdx.x * 128 + tid;

    float L = 0.f;
    #pragma unroll
    for (int z = 0; z < ZS; ++z)
        L += g_Spart[((size_t)(z * 2 + b) * 17 + 16) * Nn + n];
    const float inv = 1.f / L;

    float* Yb = g_Y + (size_t)b * NTc;
    #pragma unroll
    for (int t = 0; t < 16; ++t) {
        float a = 0.f;
        #pragma unroll
        for (int z = 0; z < ZS; ++z)
            a += g_Spart[((size_t)(z * 2 + b) * 17 + t) * Nn + n];
        Yb[t * Nn + n] = a * inv;
    }
}

// ---------------------------------------------------------------------------
// Temporal branch (unchanged from R11).
// ---------------------------------------------------------------------------
__global__ void __launch_bounds__(256) k_tempS() {
    __shared__ __align__(16) float Qs[16][132];
    __shared__ __align__(16) float Ks2[16][132];
    const int tid = threadIdx.x, b = blockIdx.y, n0 = blockIdx.x * 128;
    const float* Q = g_F + 3 * BNT + (size_t)b * NTc + (size_t)n0 * 16;
    const float* K = g_F + 4 * BNT + (size_t)b * NTc + (size_t)n0 * 16;
    #pragma unroll
    for (int r = 0; r < 2; ++r) {
        const int j = tid + r * 256, n = j >> 2, t0 = (j & 3) * 4;
        float4 qv = reinterpret_cast<const float4*>(Q)[j];
        Qs[t0 + 0][n] = qv.x; Qs[t0 + 1][n] = qv.y;
        Qs[t0 + 2][n] = qv.z; Qs[t0 + 3][n] = qv.w;
        float4 kv = reinterpret_cast<const float4*>(K)[j];
        Ks2[t0 + 0][n] = kv.x; Ks2[t0 + 1][n] = kv.y;
        Ks2[t0 + 2][n] = kv.z; Ks2[t0 + 3][n] = kv.w;
    }
    __syncthreads();
    const int t = tid >> 4, s = tid & 15;
    u64 sa = 0ULL, sb = 0ULL, sc = 0ULL, sd = 0ULL;
    #pragma unroll 8
    for (int j = 0; j < 32; j += 2) {
        ulonglong2 q4 = *reinterpret_cast<const ulonglong2*>(&Qs[t][4 * j]);
        ulonglong2 k4 = *reinterpret_cast<const ulonglong2*>(&Ks2[s][4 * j]);
        sa = fma2(q4.x, k4.x, sa); sb = fma2(q4.y, k4.y, sb);
        ulonglong2 q5 = *reinterpret_cast<const ulonglong2*>(&Qs[t][4 * j + 4]);
        ulonglong2 k5 = *reinterpret_cast<const ulonglong2*>(&Ks2[s][4 * j + 4]);
        sc = fma2(q5.x, k5.x, sc); sd = fma2(q5.y, k5.y, sd);
    }
    float2 r = upk(add2(add2(sa, sb), add2(sc, sd)));
    g_Sp[((size_t)b * 49 + blockIdx.x) * 256 + tid] = r.x + r.y;
}

__global__ void __launch_bounds__(512) k_tsoft() {
    const int tid = threadIdx.x, b = tid >> 8, ts = tid & 255;
    float a = 0.f;
    #pragma unroll
    for (int c = 0; c < 49; ++c) a += g_Sp[((size_t)b * 49 + c) * 256 + ts];
    float m = a;
    #pragma unroll
    for (int off = 1; off < 16; off <<= 1)
        m = fmaxf(m, __shfl_xor_sync(0xffffffffu, m, off));
    float e = __expf(0.25f * (a - m));
    float sum = e;
    #pragma unroll
    for (int off = 1; off < 16; off <<= 1)
        sum += __shfl_xor_sync(0xffffffffu, sum, off);
    g_A[tid] = e / sum;
}

// Temporal apply (+= at n*16+t), AFTER k_scomb. grid 98 x 256.
__global__ void k_tapply() {
    __shared__ float sA[512];
    const int tid = threadIdx.x;
    sA[tid]       = g_A[tid];
    sA[tid + 256] = g_A[tid + 256];
    __syncthreads();
    const int idx2 = blockIdx.x * 256 + tid;
    const int ng = idx2 >> 1, half = idx2 & 1;
    const int b = ng / Nn, n = ng - b * Nn;
    const float4* vp = reinterpret_cast<const float4*>(g_F + 5 * BNT + (size_t)b * NTc + n * 16);
    float v[16];
    #pragma unroll
    for (int j = 0; j < 4; ++j) {
        float4 v4 = vp[j];
        v[4 * j] = v4.x; v[4 * j + 1] = v4.y; v[4 * j + 2] = v4.z; v[4 * j + 3] = v4.w;
    }
    const float* A = &sA[b * 256];
    float4* yp = reinterpret_cast<float4*>(g_Y + (size_t)b * NTc + n * 16);
    #pragma unroll
    for (int jj = 0; jj < 2; ++jj) {
        const int j = half * 2 + jj;
        float4 y4 = yp[j];
        float o[4];
        #pragma unroll
        for (int k = 0; k < 4; ++k) {
            const int t = 4 * j + k;
            float a = 0.f;
            #pragma unroll
            for (int s = 0; s < 16; ++s) a = fmaf(A[t * 16 + s], v[s], a);
            o[k] = a;
        }
        y4.x += o[0]; y4.y += o[1]; y4.z += o[2]; y4.w += o[3];
        yp[j] = y4;
    }
}

__global__ void __launch_bounds__(64) k_out(const float* __restrict__ x,
                                            const float* __restrict__ Ww,
                                            const float* __restrict__ bw,
                                            float* __restrict__ out) {
    __shared__ float Wt[32][65];
    __shared__ __align__(16) float Ys[32][8];
    const int tid = threadIdx.x, pb = blockIdx.x;
    const int b = pb / 392, thw0 = (pb % 392) * 8;
    {
        const float4* Wg = reinterpret_cast<const float4*>(Ww);
        #pragma unroll
        for (int k = 0; k < 8; ++k) {
            const int i = tid + k * 64;
            float4 w = Wg[i];
            const int o = i >> 3, c0 = (i & 7) * 4;
            Wt[c0 + 0][o] = w.x; Wt[c0 + 1][o] = w.y;
            Wt[c0 + 2][o] = w.z; Wt[c0 + 3][o] = w.w;
        }
    }
    const float* Yb = g_Y + (size_t)b * NTc + thw0;
    {
        const int ci = tid >> 1, j = tid & 1;
        reinterpret_cast<float4*>(&Ys[ci][0])[j] =
            reinterpret_cast<const float4*>(Yb + ci * THWc)[j];
    }
    __syncthreads();
    float acc[8];
    const float bv = __ldg(&bw[tid]);
    #pragma unroll
    for (int p = 0; p < 8; ++p) acc[p] = bv;
    #pragma unroll 8
    for (int ci = 0; ci < 32; ++ci) {
        const float w = Wt[ci][tid];
        #pragma unroll
        for (int j = 0; j < 2; ++j) {
            float4 yv = reinterpret_cast<const float4*>(&Ys[ci][0])[j];
            acc[4 * j + 0] = fmaf(w, yv.x, acc[4 * j + 0]);
            acc[4 * j + 1] = fmaf(w, yv.y, acc[4 * j + 1]);
            acc[4 * j + 2] = fmaf(w, yv.z, acc[4 * j + 2]);
            acc[4 * j + 3] = fmaf(w, yv.w, acc[4 * j + 3]);
        }
    }
    const size_t off = (size_t)b * (Cc * THWc) + (size_t)tid * THWc + thw0;
    const float4* xg = reinterpret_cast<const float4*>(x + off);
    float4* og = reinterpret_cast<float4*>(out + off);
    #pragma unroll
    for (int j = 0; j < 2; ++j) {
        float4 xv = xg[j];
        og[j] = make_float4(acc[4 * j + 0] + xv.x, acc[4 * j + 1] + xv.y,
                            acc[4 * j + 2] + xv.z, acc[4 * j + 3] + xv.w);
    }
}

// ---------------------------------------------------------------------------
extern "C" void kernel_launch(void* const* d_in, const int* in_sizes, int n_in,
                              void* d_out, int out_size) {
    (void)in_sizes; (void)n_in; (void)out_size;
    const float* x   = (const float*)d_in[0];
    const float* Wqs = (const float*)d_in[1];  const float* bqs = (const float*)d_in[2];
    const float* Wks = (const float*)d_in[3];  const float* bks = (const float*)d_in[4];
    const float* Wvs = (const float*)d_in[5];  const float* bvs = (const float*)d_in[6];
    const float* Wqt = (const float*)d_in[7];  const float* bqt = (const float*)d_in[8];
    const float* Wkt = (const float*)d_in[9];  const float* bkt = (const float*)d_in[10];
    const float* Wvt = (const float*)d_in[11]; const float* bvt = (const float*)d_in[12];
    const float* Ww  = (const float*)d_in[13]; const float* bw  = (const float*)d_in[14];
    float* out = (float*)d_out;

    k_proj6<<<784, 96>>>(x, Wqs, bqs, Wks, bks, Wvs, bvs,
                            Wqt, bqt, Wkt, bkt, Wvt, bvt);
    k_prep<<<dim3(49, 2), 256>>>();
    k_sfmma<<<dim3(49, 2, ZS), 128>>>();
    k_tempS<<<dim3(49, 2), 256>>>();
    k_tsoft<<<1, 512>>>();
    k_scomb<<<dim3(49, 2), 128>>>();
    k_tapply<<<98, 256>>>();
    k_out<<<784, 64>>>(x, Ww, bw, out);
}